// round 13
// baseline (speedup 1.0000x reference)
#include <cuda_runtime.h>

// ---------------------------------------------------------------------------
// VQEmbedding, exact fp32 FFMA2 GEMM + argmin. Occ-3 edition (TK=32).
//   G_nk = seq fp32 FMA over d ; dist = rn( rn(S+T) - 2G ) ; argmin low-idx
// Output layout (float32): [ out : 8388608 | loss : 1 | indices : 131072 ]
// ---------------------------------------------------------------------------

#define TN 128
#define TK 32
#define APAD 132           // A row stride (floats)
#define WPAD 36            // W chunk row stride (floats)
#define NUM_K 1024
#define D 64
#define WOFF (D * WPAD)    // one W buffer, floats (2304)
#define NTILES 1024
#define OUT_ELEMS 8388608
#define LOSS_OFF  8388608
#define IDX_OFF   8388609

// smem float offsets
#define A_F    0                       // [64][132]      = 8448 floats
#define W_F    8448                    // 2 x [64][36]   = 4608
#define TS_F   13056                   // [1024]
#define SS_F   14080                   // [128]
#define BK_F   14208                   // [128] (ints)
#define RED_F  14336                   // [8]
#define SMEM_FLOATS 14344              // ~57.4 KB

__device__ __align__(16) float g_T[NUM_K];        // exact sum(w^2)
__device__ __align__(16) float g_wT[D * NUM_K];   // w transposed [d][k]
__device__ double g_loss_sum;
__device__ unsigned g_done;

typedef unsigned long long ull;

__device__ __forceinline__ ull pack2(float x, float y) {
    ull r;
    asm("mov.b64 %0, {%1, %2};" : "=l"(r)
        : "r"(__float_as_uint(x)), "r"(__float_as_uint(y)));
    return r;
}
__device__ __forceinline__ void unpack2(ull p, float &x, float &y) {
    unsigned a, b;
    asm("mov.b64 {%0, %1}, %2;" : "=r"(a), "=r"(b) : "l"(p));
    x = __uint_as_float(a); y = __uint_as_float(b);
}
#define FMA2(d, a, b, c) \
    asm("fma.rn.f32x2 %0, %1, %2, %3;" : "=l"(d) : "l"(a), "l"(b), "l"(c))

// ---------------------------------------------------------------------------
// Prep: 16 blocks transpose w -> g_wT, exact T_k, zero loss + done counter.
// ---------------------------------------------------------------------------
__global__ __launch_bounds__(256)
void vq_prep(const float* __restrict__ w) {
    __shared__ float s[64][65];
    const int t = threadIdx.x;
    const int kb = blockIdx.x * 64;
    if (blockIdx.x == 0 && t == 0) { g_loss_sum = 0.0; g_done = 0u; }
    {
        int k = t >> 2, dq = (t & 3) << 4;
        const float4* src = (const float4*)(w + (kb + k) * D + dq);
        float4 v0 = src[0], v1 = src[1], v2 = src[2], v3 = src[3];
        s[dq+ 0][k]=v0.x; s[dq+ 1][k]=v0.y; s[dq+ 2][k]=v0.z; s[dq+ 3][k]=v0.w;
        s[dq+ 4][k]=v1.x; s[dq+ 5][k]=v1.y; s[dq+ 6][k]=v1.z; s[dq+ 7][k]=v1.w;
        s[dq+ 8][k]=v2.x; s[dq+ 9][k]=v2.y; s[dq+10][k]=v2.z; s[dq+11][k]=v2.w;
        s[dq+12][k]=v3.x; s[dq+13][k]=v3.y; s[dq+14][k]=v3.z; s[dq+15][k]=v3.w;
    }
    __syncthreads();
    {
        int d = t >> 2, kq = (t & 3) << 4;
        float4* dst = (float4*)(g_wT + d * NUM_K + kb + kq);
        #pragma unroll
        for (int j = 0; j < 4; j++) {
            float4 o;
            o.x = s[d][kq + 4*j + 0]; o.y = s[d][kq + 4*j + 1];
            o.z = s[d][kq + 4*j + 2]; o.w = s[d][kq + 4*j + 3];
            dst[j] = o;
        }
    }
    if (t < 64) {
        float acc = 0.f;
        #pragma unroll
        for (int d = 0; d < D; d++) {
            float v = s[d][t];
            acc = __fadd_rn(acc, __fmul_rn(v, v));
        }
        g_T[kb + t] = acc;
    }
}

// ---------------------------------------------------------------------------
__device__ __forceinline__ unsigned s2u(const void* p) {
    unsigned a;
    asm("{ .reg .u64 t; cvta.to.shared.u64 t, %1; cvt.u32.u64 %0, t; }"
        : "=r"(a) : "l"(p));
    return a;
}

// stage one 64(d) x 32(k) W chunk (g_wT cols c*32..) into buffer buf
__device__ __forceinline__ void stage_chunk(float* smf, int buf, int c, int tid) {
    float* dst = smf + W_F + buf * WOFF;
    const float* src = g_wT + c * TK;
    #pragma unroll
    for (int i = 0; i < 2; i++) {
        int idx = tid + i * 256;           // 0..511 float4 chunks
        int d = idx >> 3, kk = (idx & 7) << 2;
        unsigned sa = s2u(dst + d * WPAD + kk);
        asm volatile("cp.async.cg.shared.global [%0], [%1], 16;"
                     :: "r"(sa), "l"(src + d * NUM_K + kk));
    }
    asm volatile("cp.async.commit_group;" ::: "memory");
}

extern __shared__ float smf[];

__global__ __launch_bounds__(256, 3)
void vq_main(const float* __restrict__ x, const float* __restrict__ w,
             float* __restrict__ out) {
    float* As  = smf + A_F;
    float* tsp = smf + TS_F;
    float* Ss  = smf + SS_F;
    int*   bks = (int*)(smf + BK_F);
    float* red = smf + RED_F;

    const int tid = threadIdx.x;
    const int tx = tid & 15;          // k: 2 codes
    const int ty = tid >> 4;          // n: 8 pixels
    const int n0 = blockIdx.x * TN;
    const int b  = n0 >> 12;
    const int hw0 = n0 & 4095;
    const float* xb = x + ((size_t)b << 18);

    // stage W chunk 0 + T table
    stage_chunk(smf, 0, 0, tid);
    {
        unsigned sa = s2u(tsp + tid * 4);
        asm volatile("cp.async.cg.shared.global [%0], [%1], 16;"
                     :: "r"(sa), "l"(g_T + tid * 4));
        asm volatile("cp.async.commit_group;" ::: "memory");
    }
    for (int e = tid; e < TN * D; e += 256) {
        int nl = e & 127, d = e >> 7;
        As[d * APAD + nl] = xb[(d << 12) + hw0 + nl];
    }
    asm volatile("cp.async.wait_group 0;" ::: "memory");
    __syncthreads();

    if (tid < TN) {                    // exact S_n, sequential d
        float s = 0.f;
        #pragma unroll
        for (int d = 0; d < D; d++) {
            float v = As[d * APAD + tid];
            s = __fadd_rn(s, __fmul_rn(v, v));
        }
        Ss[tid] = s;
    }
    __syncthreads();

    float s8[8];
    #pragma unroll
    for (int i = 0; i < 8; i++) s8[i] = Ss[(ty << 3) + i];

    float bestv[8];
    int   besti[8];
    #pragma unroll
    for (int i = 0; i < 8; i++) { bestv[i] = 3.4e38f; besti[i] = 0; }

    #pragma unroll 1
    for (int c = 0; c < 32; c++) {
        const float* cur = smf + W_F + (c & 1) * WOFF;
        if (c < 31) stage_chunk(smf, (c + 1) & 1, c + 1, tid);

        const int kb = (c << 5) + (tx << 1);
        float tk0 = tsp[kb], tk1 = tsp[kb + 1];

        ull acc[8];
        #pragma unroll
        for (int i = 0; i < 8; i++) acc[i] = 0ull;

        const float* Ar0 = As + (ty << 3);
        const float* Wr0 = cur + (tx << 1);
        #pragma unroll 4
        for (int d = 0; d < D; d++) {
            const float* Ar = Ar0 + d * APAD;
            ulonglong2 a01 = ((const ulonglong2*)Ar)[0];   // (n0,n1),(n2,n3)
            ulonglong2 a23 = ((const ulonglong2*)Ar)[1];   // (n4,n5),(n6,n7)
            float2 wv = *(const float2*)(Wr0 + d * WPAD);
            ull wd0 = pack2(wv.x, wv.x);
            ull wd1 = pack2(wv.y, wv.y);
            FMA2(acc[0], a01.x, wd0, acc[0]);
            FMA2(acc[1], a01.y, wd0, acc[1]);
            FMA2(acc[2], a23.x, wd0, acc[2]);
            FMA2(acc[3], a23.y, wd0, acc[3]);
            FMA2(acc[4], a01.x, wd1, acc[4]);
            FMA2(acc[5], a01.y, wd1, acc[5]);
            FMA2(acc[6], a23.x, wd1, acc[6]);
            FMA2(acc[7], a23.y, wd1, acc[7]);
        }

        // exact scoring: d = rn( rn(S+T) - 2G ); running argmin (low idx ties)
        float tkv[2] = {tk0, tk1};
        #pragma unroll
        for (int k = 0; k < 2; k++) {
            float T = tkv[k];
            int kg = kb + k;
            #pragma unroll
            for (int np = 0; np < 4; np++) {
                float G0, G1;
                unpack2(acc[k * 4 + np], G0, G1);
                float u0 = __fadd_rn(s8[2*np],     T);
                float u1 = __fadd_rn(s8[2*np + 1], T);
                float d0 = __fmaf_rn(-2.f, G0, u0);
                float d1 = __fmaf_rn(-2.f, G1, u1);
                if (d0 < bestv[2*np]) { bestv[2*np] = d0; besti[2*np] = kg; }
                if (d1 < bestv[2*np+1]) { bestv[2*np+1] = d1; besti[2*np+1] = kg; }
            }
        }

        if (c < 31) asm volatile("cp.async.wait_group 0;" ::: "memory");
        __syncthreads();
    }

    // reduce over the 16 tx lanes; smaller index wins exact ties
    #pragma unroll
    for (int i = 0; i < 8; i++) {
        float v = bestv[i]; int bi = besti[i];
        #pragma unroll
        for (int off = 8; off; off >>= 1) {
            float ov = __shfl_xor_sync(0xffffffffu, v, off);
            int   oi = __shfl_xor_sync(0xffffffffu, bi, off);
            if (ov < v || (ov == v && oi < bi)) { v = ov; bi = oi; }
        }
        if (tx == 0) bks[(ty << 3) + i] = bi;
    }
    __syncthreads();

    // gather chosen codewords: 2 threads per pixel; overlay needs [64][132]
    // floats = 8448; W_F..W_F+4608 + TS area reuse is NOT safe (tsp alive? no:
    // tsp unused after the chunk loop) -> overlay at A? As is still needed for
    // loss. Use W buffers + TS region: 4608 + 1024 < 8448, so extend into SS?
    // SS/bks still needed. Instead scatter directly from registers per pixel
    // pair with smem staging of 2 rows at a time is complex; simplest: reuse
    // W region with APAD=66 stride (64*66=4224 <= 4608 floats).
    {
        float* wout = smf + W_F;       // [64][66] overlay, fits in W buffers
        int p = tid >> 1, half = tid & 1;
        int k = bks[p];
        const float4* src = (const float4*)(w + (k << 6)) + half * 8;
        #pragma unroll
        for (int j = 0; j < 8; j++) {
            float4 v = src[j];
            int d = half * 32 + j * 4;
            // transposed write: wout[p][d] layout [128][33]? -> use [p*33+d/2]?
            // keep [d][p] with stride 66 is impossible (needs 128 wide).
            // Store [p][d] instead: row p, stride 66 covers d 0..63.
            wout[p * 33 + 0] = wout[p * 33 + 0]; // placeholder no-op
            (void)v; (void)d;
        }
    }
    // NOTE: the above overlay attempt is abandoned; do direct gather-scatter:
    __syncthreads();
    {
        // Each pair of threads writes one pixel across d: strided but correct.
        // To keep stores coalesced along pixels, regroup: thread e handles
        // elements e, e+256, ... of the [d][n] tile, loading w[bks[n]][d]
        // directly from L2-resident codebook (scattered 4B loads, but the
        // codebook is hot in L2 and total loads = 8192 per CTA).
        const size_t ob = ((size_t)b << 18);
        float lsum = 0.f;
        for (int e = tid; e < TN * D; e += 256) {
            int nl = e & 127, d = e >> 7;
            float wv = w[(bks[nl] << 6) + d];
            float xv = As[d * APAD + nl];
            out[ob + (d << 12) + hw0 + nl] = wv;
            float df = xv - wv;
            lsum += df * df;
        }
        if (tid < TN) out[IDX_OFF + n0 + tid] = (float)bks[tid];

        #pragma unroll
        for (int off = 16; off; off >>= 1)
            lsum += __shfl_xor_sync(0xffffffffu, lsum, off);
        if ((tid & 31) == 0) red[tid >> 5] = lsum;
        __syncthreads();
        if (tid == 0) {
            float s = 0.f;
            #pragma unroll
            for (int i = 0; i < 8; i++) s += red[i];
            atomicAdd(&g_loss_sum, (double)s);
            __threadfence();
            unsigned old = atomicAdd(&g_done, 1u);
            if (old == NTILES - 1) {
                __threadfence();
                double ls = g_loss_sum;
                out[LOSS_OFF] = (float)(1.25 * ls / (double)OUT_ELEMS);
            }
        }
    }
}

// ---------------------------------------------------------------------------
extern "C" void kernel_launch(void* const* d_in, const int* in_sizes, int n_in,
                              void* d_out, int out_size) {
    const float* x = (const float*)d_in[0];   // [32,64,64,64] f32
    const float* w = (const float*)d_in[1];   // [1024,64] f32
    float* out = (float*)d_out;

    const int SMEM_BYTES = SMEM_FLOATS * 4;
    cudaFuncSetAttribute(vq_main, cudaFuncAttributeMaxDynamicSharedMemorySize,
                         SMEM_BYTES);

    vq_prep<<<16, 256>>>(w);
    vq_main<<<NTILES, 256, SMEM_BYTES>>>(x, w, out);
}

// round 14
// speedup vs baseline: 1.2586x; 1.2586x over previous
#include <cuda_runtime.h>

// ---------------------------------------------------------------------------
// VQEmbedding, exact fp32 FFMA2 GEMM + argmin. TK=64, occ-2, 4-buffer ring.
//   G_nk = seq fp32 FMA over d ; dist = rn( rn(S+T) - 2G ) ; argmin low-idx
// Output layout (float32): [ out : 8388608 | loss : 1 | indices : 131072 ]
// ---------------------------------------------------------------------------

#define TN 128
#define TK 64
#define APAD 132           // A row stride (floats)
#define WPAD 68            // W chunk row stride (floats)
#define NUM_K 1024
#define D 64
#define WOFF (D * WPAD)    // one W buffer, floats (4352)
#define NBUF 4
#define NTILES 1024
#define OUT_ELEMS 8388608
#define LOSS_OFF  8388608
#define IDX_OFF   8388609

// smem float offsets
#define A_F    0                       // [64][132]        = 8448
#define W_F    8448                    // 4 x [64][68]     = 17408
#define TS_F   25856                   // [1024]
#define SS_F   26880                   // [128]
#define BK_F   27008                   // [128] ints
#define RED_F  27136                   // [8]
#define SMEM_FLOATS 27144              // ~108.6 KB

__device__ __align__(16) float g_T[NUM_K];        // exact sum(w^2)
__device__ __align__(16) float g_wT[D * NUM_K];   // w transposed [d][k]
__device__ double g_loss_sum;
__device__ unsigned g_done;

typedef unsigned long long ull;

__device__ __forceinline__ ull pack2(float x, float y) {
    ull r;
    asm("mov.b64 %0, {%1, %2};" : "=l"(r)
        : "r"(__float_as_uint(x)), "r"(__float_as_uint(y)));
    return r;
}
__device__ __forceinline__ void unpack2(ull p, float &x, float &y) {
    unsigned a, b;
    asm("mov.b64 {%0, %1}, %2;" : "=r"(a), "=r"(b) : "l"(p));
    x = __uint_as_float(a); y = __uint_as_float(b);
}
#define FMA2(d, a, b, c) \
    asm("fma.rn.f32x2 %0, %1, %2, %3;" : "=l"(d) : "l"(a), "l"(b), "l"(c))

// ---------------------------------------------------------------------------
// Prep: 16 blocks transpose w -> g_wT, exact T_k, zero loss + done counter.
// ---------------------------------------------------------------------------
__global__ __launch_bounds__(256)
void vq_prep(const float* __restrict__ w) {
    __shared__ float s[64][65];
    const int t = threadIdx.x;
    const int kb = blockIdx.x * 64;
    if (blockIdx.x == 0 && t == 0) { g_loss_sum = 0.0; g_done = 0u; }
    {
        int k = t >> 2, dq = (t & 3) << 4;
        const float4* src = (const float4*)(w + (kb + k) * D + dq);
        float4 v0 = src[0], v1 = src[1], v2 = src[2], v3 = src[3];
        s[dq+ 0][k]=v0.x; s[dq+ 1][k]=v0.y; s[dq+ 2][k]=v0.z; s[dq+ 3][k]=v0.w;
        s[dq+ 4][k]=v1.x; s[dq+ 5][k]=v1.y; s[dq+ 6][k]=v1.z; s[dq+ 7][k]=v1.w;
        s[dq+ 8][k]=v2.x; s[dq+ 9][k]=v2.y; s[dq+10][k]=v2.z; s[dq+11][k]=v2.w;
        s[dq+12][k]=v3.x; s[dq+13][k]=v3.y; s[dq+14][k]=v3.z; s[dq+15][k]=v3.w;
    }
    __syncthreads();
    {
        int d = t >> 2, kq = (t & 3) << 4;
        float4* dst = (float4*)(g_wT + d * NUM_K + kb + kq);
        #pragma unroll
        for (int j = 0; j < 4; j++) {
            float4 o;
            o.x = s[d][kq + 4*j + 0]; o.y = s[d][kq + 4*j + 1];
            o.z = s[d][kq + 4*j + 2]; o.w = s[d][kq + 4*j + 3];
            dst[j] = o;
        }
    }
    if (t < 64) {
        float acc = 0.f;
        #pragma unroll
        for (int d = 0; d < D; d++) {
            float v = s[d][t];
            acc = __fadd_rn(acc, __fmul_rn(v, v));
        }
        g_T[kb + t] = acc;
    }
}

// ---------------------------------------------------------------------------
__device__ __forceinline__ unsigned s2u(const void* p) {
    unsigned a;
    asm("{ .reg .u64 t; cvta.to.shared.u64 t, %1; cvt.u32.u64 %0, t; }"
        : "=r"(a) : "l"(p));
    return a;
}

// stage one 64(d) x 64(k) W chunk (g_wT cols c*64..) into buffer buf
__device__ __forceinline__ void stage_chunk(float* smf, int buf, int c, int tid) {
    float* dst = smf + W_F + buf * WOFF;
    const float* src = g_wT + c * TK;
    #pragma unroll
    for (int i = 0; i < 4; i++) {
        int idx = tid + i * 256;           // 0..1023 float4 chunks
        int d = idx >> 4, kk = (idx & 15) << 2;
        unsigned sa = s2u(dst + d * WPAD + kk);
        asm volatile("cp.async.cg.shared.global [%0], [%1], 16;"
                     :: "r"(sa), "l"(src + d * NUM_K + kk));
    }
}

// one 128x64 GEMM chunk + exact scoring into running argmin
__device__ __forceinline__ void gemm_chunk(const float* As, const float* cur,
                                           const float* tsp, const float* Ss,
                                           int kc, int tx, int ty,
                                           float bestv[8], int besti[8]) {
    const int kb = kc + (tx << 2);

    ull acc[16];
    #pragma unroll
    for (int i = 0; i < 16; i++) acc[i] = 0ull;

    const float* Ar0 = As + (ty << 3);
    const float* Wr0 = cur + (tx << 2);
    #pragma unroll 8
    for (int d = 0; d < D; d++) {
        const float* Ar = Ar0 + d * APAD;
        const float* Wr = Wr0 + d * WPAD;
        ulonglong2 a01 = ((const ulonglong2*)Ar)[0];   // (n0,n1),(n2,n3)
        ulonglong2 a23 = ((const ulonglong2*)Ar)[1];   // (n4,n5),(n6,n7)
        float4 wv = *(const float4*)Wr;
        ull wd0 = pack2(wv.x, wv.x), wd1 = pack2(wv.y, wv.y);
        ull wd2 = pack2(wv.z, wv.z), wd3 = pack2(wv.w, wv.w);
        FMA2(acc[ 0], a01.x, wd0, acc[ 0]);
        FMA2(acc[ 1], a01.y, wd0, acc[ 1]);
        FMA2(acc[ 2], a23.x, wd0, acc[ 2]);
        FMA2(acc[ 3], a23.y, wd0, acc[ 3]);
        FMA2(acc[ 4], a01.x, wd1, acc[ 4]);
        FMA2(acc[ 5], a01.y, wd1, acc[ 5]);
        FMA2(acc[ 6], a23.x, wd1, acc[ 6]);
        FMA2(acc[ 7], a23.y, wd1, acc[ 7]);
        FMA2(acc[ 8], a01.x, wd2, acc[ 8]);
        FMA2(acc[ 9], a01.y, wd2, acc[ 9]);
        FMA2(acc[10], a23.x, wd2, acc[10]);
        FMA2(acc[11], a23.y, wd2, acc[11]);
        FMA2(acc[12], a01.x, wd3, acc[12]);
        FMA2(acc[13], a01.y, wd3, acc[13]);
        FMA2(acc[14], a23.x, wd3, acc[14]);
        FMA2(acc[15], a23.y, wd3, acc[15]);
    }

    // exact scoring: d = rn( rn(S+T) - 2G ); running argmin (low idx ties).
    // S/T re-loaded from smem here (broadcast hits) to keep the d-loop lean.
    #pragma unroll
    for (int k = 0; k < 4; k++) {
        float T = tsp[kb + k];
        int kg = kb + k;
        #pragma unroll
        for (int np = 0; np < 4; np++) {
            float G0, G1;
            unpack2(acc[k * 4 + np], G0, G1);
            float u0 = __fadd_rn(Ss[(ty << 3) + 2 * np],     T);
            float u1 = __fadd_rn(Ss[(ty << 3) + 2 * np + 1], T);
            float d0 = __fmaf_rn(-2.f, G0, u0);
            float d1 = __fmaf_rn(-2.f, G1, u1);
            if (d0 < bestv[2*np])   { bestv[2*np]   = d0; besti[2*np]   = kg; }
            if (d1 < bestv[2*np+1]) { bestv[2*np+1] = d1; besti[2*np+1] = kg; }
        }
    }
}

extern __shared__ float smf[];

__global__ __launch_bounds__(256, 2)
void vq_main(const float* __restrict__ x, const float* __restrict__ w,
             float* __restrict__ out) {
    float* As  = smf + A_F;
    float* tsp = smf + TS_F;
    float* Ss  = smf + SS_F;
    int*   bks = (int*)(smf + BK_F);
    float* red = smf + RED_F;

    const int tid = threadIdx.x;
    const int tx = tid & 15;          // k: 4 codes
    const int ty = tid >> 4;          // n: 8 pixels
    const int n0 = blockIdx.x * TN;
    const int b  = n0 >> 12;
    const int hw0 = n0 & 4095;
    const float* xb = x + ((size_t)b << 18);

    // prologue: stage chunks 0,1 + T table; load A tile
    stage_chunk(smf, 0, 0, tid);
    stage_chunk(smf, 1, 1, tid);
    {
        unsigned sa = s2u(tsp + tid * 4);
        asm volatile("cp.async.cg.shared.global [%0], [%1], 16;"
                     :: "r"(sa), "l"(g_T + tid * 4));
    }
    asm volatile("cp.async.commit_group;" ::: "memory");
    for (int e = tid; e < TN * D; e += 256) {
        int nl = e & 127, d = e >> 7;
        As[d * APAD + nl] = xb[(d << 12) + hw0 + nl];
    }
    asm volatile("cp.async.wait_group 0;" ::: "memory");
    __syncthreads();

    if (tid < TN) {                    // exact S_n, sequential d
        float s = 0.f;
        #pragma unroll
        for (int d = 0; d < D; d++) {
            float v = As[d * APAD + tid];
            s = __fadd_rn(s, __fmul_rn(v, v));
        }
        Ss[tid] = s;
    }

    float bestv[8];
    int   besti[8];
    #pragma unroll
    for (int i = 0; i < 8; i++) { bestv[i] = 3.4e38f; besti[i] = 0; }

    #pragma unroll 1
    for (int c = 0; c < 16; c += 2) {
        __syncthreads();   // all warps done with bufs (c+2)&3,(c+3)&3 (iter c-2)
                           // and, at c=0, Ss is visible
        if (c + 2 < 16) {
            stage_chunk(smf, (c + 2) & 3, c + 2, tid);
            stage_chunk(smf, (c + 3) & 3, c + 3, tid);
            asm volatile("cp.async.commit_group;" ::: "memory");
            asm volatile("cp.async.wait_group 1;" ::: "memory");  // c,c+1 ready
        } else {
            asm volatile("cp.async.wait_group 0;" ::: "memory");
        }
        gemm_chunk(As, smf + W_F + (c & 3) * WOFF, tsp, Ss,
                   c << 6, tx, ty, bestv, besti);
        gemm_chunk(As, smf + W_F + ((c + 1) & 3) * WOFF, tsp, Ss,
                   (c + 1) << 6, tx, ty, bestv, besti);
    }
    __syncthreads();

    // reduce over the 16 tx lanes; smaller index wins exact ties
    #pragma unroll
    for (int i = 0; i < 8; i++) {
        float v = bestv[i]; int bi = besti[i];
        #pragma unroll
        for (int off = 8; off; off >>= 1) {
            float ov = __shfl_xor_sync(0xffffffffu, v, off);
            int   oi = __shfl_xor_sync(0xffffffffu, bi, off);
            if (ov < v || (ov == v && oi < bi)) { v = ov; bi = oi; }
        }
        if (tx == 0) bks[(ty << 3) + i] = bi;
    }
    __syncthreads();

    // gather chosen codewords: 2 threads per pixel into overlay wout[64][132]
    float* wout = smf + W_F;           // 17408 floats >= 8448 overlay
    {
        int p = tid >> 1, half = tid & 1;
        int k = bks[p];
        const float4* src = (const float4*)(w + (k << 6)) + half * 8;
        #pragma unroll
        for (int j = 0; j < 8; j++) {
            float4 v = src[j];
            int d = half * 32 + j * 4;
            wout[(d + 0) * APAD + p] = v.x;
            wout[(d + 1) * APAD + p] = v.y;
            wout[(d + 2) * APAD + p] = v.z;
            wout[(d + 3) * APAD + p] = v.w;
        }
    }
    __syncthreads();

    const size_t ob = ((size_t)b << 18);
    float lsum = 0.f;
    for (int e = tid; e < TN * D; e += 256) {
        int nl = e & 127, d = e >> 7;
        float wv = wout[d * APAD + nl];
        float xv = As[d * APAD + nl];
        out[ob + (d << 12) + hw0 + nl] = wv;
        float df = xv - wv;
        lsum += df * df;
    }
    if (tid < TN) out[IDX_OFF + n0 + tid] = (float)bks[tid];

    #pragma unroll
    for (int off = 16; off; off >>= 1)
        lsum += __shfl_xor_sync(0xffffffffu, lsum, off);
    if ((tid & 31) == 0) red[tid >> 5] = lsum;
    __syncthreads();
    if (tid == 0) {
        float s = 0.f;
        #pragma unroll
        for (int i = 0; i < 8; i++) s += red[i];
        atomicAdd(&g_loss_sum, (double)s);
        __threadfence();
        unsigned old = atomicAdd(&g_done, 1u);
        if (old == NTILES - 1) {       // last CTA finalizes the loss
            __threadfence();
            double ls = g_loss_sum;
            out[LOSS_OFF] = (float)(1.25 * ls / (double)OUT_ELEMS);
        }
    }
}

// ---------------------------------------------------------------------------
extern "C" void kernel_launch(void* const* d_in, const int* in_sizes, int n_in,
                              void* d_out, int out_size) {
    const float* x = (const float*)d_in[0];   // [32,64,64,64] f32
    const float* w = (const float*)d_in[1];   // [1024,64] f32
    float* out = (float*)d_out;

    const int SMEM_BYTES = SMEM_FLOATS * 4;
    cudaFuncSetAttribute(vq_main, cudaFuncAttributeMaxDynamicSharedMemorySize,
                         SMEM_BYTES);

    vq_prep<<<16, 256>>>(w);
    vq_main<<<NTILES, 256, SMEM_BYTES>>>(x, w, out);
}